// round 9
// baseline (speedup 1.0000x reference)
#include <cuda_runtime.h>
#include <math.h>

#define N_NODES 8192
#define N_EDGES 32768
#define HID     8
#define FEAT    11          // HID + 3
#define EG      (N_EDGES / 4)   // 8192 float4 groups per row
#define SLAB    32
#define NSLABS  (N_NODES / SLAB) // 256

// Scratch: recovered gather indices (each edge written exactly once per scan)
__device__ int g_idx_i[N_EDGES];
__device__ int g_idx_o[N_EDGES];

// ---------------------------------------------------------------------------
// Kernel 1: recover one-hot indices from dense incidence matrices.
// R is [N_NODES, N_EDGES] row-major. Column e has exactly one 1.0.
// idx[e] = sum_n R[n,e] * (n+1)  - 1   (branch-free FFMA accumulation)
// Proven-best access pattern (R1): float4/thread, unroll 8, no data-dependent
// branches. SLAB=32 (16384 CTAs): finer tail granularity (~110 sequential
// CTAs/SM -> <1% finish spread). R6->R7 confirmed smaller slabs help.
// ---------------------------------------------------------------------------
__global__ void __launch_bounds__(256)
scan_onehot_kernel(const float* __restrict__ Ri, const float* __restrict__ Ro)
{
    const int g    = blockIdx.x * blockDim.x + threadIdx.x;  // float4 group (4 edges)
    const int slab = blockIdx.y;
    const float* __restrict__ R = (blockIdx.z == 0) ? Ri : Ro;
    int* __restrict__ idx       = (blockIdx.z == 0) ? g_idx_i : g_idx_o;

    const float4* __restrict__ p =
        reinterpret_cast<const float4*>(R) + (size_t)slab * SLAB * EG + g;

    float fx = 0.f, fy = 0.f, fz = 0.f, fw = 0.f;
    const int n0 = slab * SLAB;

#pragma unroll 8
    for (int k = 0; k < SLAB; ++k) {
        float4 v = __ldcs(p);          // streaming load, read-once data
        p += EG;
        float w = (float)(n0 + k + 1); // +1 so a hit at n=0 is distinguishable
        fx = fmaf(v.x, w, fx);
        fy = fmaf(v.y, w, fy);
        fz = fmaf(v.z, w, fz);
        fw = fmaf(v.w, w, fw);
    }

    const int e = 4 * g;
    if (fx != 0.f) idx[e + 0] = (int)fx - 1;
    if (fy != 0.f) idx[e + 1] = (int)fy - 1;
    if (fz != 0.f) idx[e + 2] = (int)fz - 1;
    if (fw != 0.f) idx[e + 3] = (int)fw - 1;
}

// ---------------------------------------------------------------------------
// Kernel 2: fused gather + 2-layer MLP per edge.
// B[e] = [X[idx_o[e]], X[idx_i[e]]] (22) -> tanh(.@W1+b1) (8) -> sigmoid(.@W2+b2)
// 512 CTAs x 64 threads: ~3.5 CTAs per SM covers all SMs and hides gather
// latency (vs 128 CTAs leaving 2/3 of SMs idle).
// ---------------------------------------------------------------------------
__global__ void __launch_bounds__(64)
edge_mlp_kernel(const float* __restrict__ X,
                const float* __restrict__ W1, const float* __restrict__ b1,
                const float* __restrict__ W2, const float* __restrict__ b2,
                float* __restrict__ out)
{
    __shared__ float sW1[2 * FEAT * HID];  // [22][8] = 176 floats
    __shared__ float sb1[HID];
    __shared__ float sW2[HID];
    __shared__ float sb2;

    const int t = threadIdx.x;
    for (int i = t; i < 2 * FEAT * HID; i += blockDim.x) sW1[i] = W1[i];
    if (t < HID)  { sb1[t] = b1[t]; sW2[t] = W2[t]; }
    if (t == 0)   sb2 = b2[0];
    __syncthreads();

    const int e = blockIdx.x * blockDim.x + t;
    if (e >= N_EDGES) return;

    const float* __restrict__ xo = X + (size_t)g_idx_o[e] * FEAT;
    const float* __restrict__ xi = X + (size_t)g_idx_i[e] * FEAT;

    float h[HID];
#pragma unroll
    for (int j = 0; j < HID; ++j) h[j] = sb1[j];

#pragma unroll
    for (int f = 0; f < FEAT; ++f) {
        const float v = __ldg(xo + f);
#pragma unroll
        for (int j = 0; j < HID; ++j) h[j] = fmaf(v, sW1[f * HID + j], h[j]);
    }
#pragma unroll
    for (int f = 0; f < FEAT; ++f) {
        const float v = __ldg(xi + f);
#pragma unroll
        for (int j = 0; j < HID; ++j) h[j] = fmaf(v, sW1[(FEAT + f) * HID + j], h[j]);
    }

    float s = sb2;
#pragma unroll
    for (int j = 0; j < HID; ++j) s = fmaf(tanhf(h[j]), sW2[j], s);

    out[e] = 1.0f / (1.0f + expf(-s));
}

// ---------------------------------------------------------------------------
// Inputs (metadata order): X, Ri, Ro, W1, b1, W2, b2. Output: float [N_EDGES].
// ---------------------------------------------------------------------------
extern "C" void kernel_launch(void* const* d_in, const int* in_sizes, int n_in,
                              void* d_out, int out_size)
{
    const float* X  = (const float*)d_in[0];
    const float* Ri = (const float*)d_in[1];
    const float* Ro = (const float*)d_in[2];
    const float* W1 = (const float*)d_in[3];
    const float* b1 = (const float*)d_in[4];
    const float* W2 = (const float*)d_in[5];
    const float* b2 = (const float*)d_in[6];
    float* out = (float*)d_out;

    // Scan: 32 edge-blocks x 256 n-slabs x 2 matrices = 16384 CTAs
    dim3 sgrid(EG / 256, NSLABS, 2);
    scan_onehot_kernel<<<sgrid, 256>>>(Ri, Ro);

    // MLP: 512 CTAs x 64 threads = 32768 edges
    edge_mlp_kernel<<<N_EDGES / 64, 64>>>(X, W1, b1, W2, b2, out);
}

// round 10
// speedup vs baseline: 1.0100x; 1.0100x over previous
#include <cuda_runtime.h>
#include <math.h>

#define N_NODES 8192
#define N_EDGES 32768
#define HID     8
#define FEAT    11          // HID + 3
#define EG      (N_EDGES / 4)   // 8192 float4 groups per row
#define SLAB    64
#define NSLABS  (N_NODES / SLAB) // 128

// Scratch: recovered gather indices (each edge written exactly once per scan)
__device__ int g_idx_i[N_EDGES];
__device__ int g_idx_o[N_EDGES];

// ---------------------------------------------------------------------------
// Kernel 1: recover one-hot indices from dense incidence matrices.
// R is [N_NODES, N_EDGES] row-major. Column e has exactly one 1.0.
// idx[e] = sum_n R[n,e] * (n+1)  - 1   (branch-free FFMA accumulation)
// Measured-optimal config (R7, 291.6us): 1M threads, float4/thread, unroll 8,
// SLAB=64 (U-curve optimum: 128->294, 64->291.6, 32->297).
// PDL trigger after stores lets the MLP kernel launch during the drain.
// ---------------------------------------------------------------------------
__global__ void __launch_bounds__(256)
scan_onehot_kernel(const float* __restrict__ Ri, const float* __restrict__ Ro)
{
    const int g    = blockIdx.x * blockDim.x + threadIdx.x;  // float4 group (4 edges)
    const int slab = blockIdx.y;
    const float* __restrict__ R = (blockIdx.z == 0) ? Ri : Ro;
    int* __restrict__ idx       = (blockIdx.z == 0) ? g_idx_i : g_idx_o;

    const float4* __restrict__ p =
        reinterpret_cast<const float4*>(R) + (size_t)slab * SLAB * EG + g;

    float fx = 0.f, fy = 0.f, fz = 0.f, fw = 0.f;
    const int n0 = slab * SLAB;

#pragma unroll 8
    for (int k = 0; k < SLAB; ++k) {
        float4 v = __ldcs(p);          // streaming load, read-once data
        p += EG;
        float w = (float)(n0 + k + 1); // +1 so a hit at n=0 is distinguishable
        fx = fmaf(v.x, w, fx);
        fy = fmaf(v.y, w, fy);
        fz = fmaf(v.z, w, fz);
        fw = fmaf(v.w, w, fw);
    }

    const int e = 4 * g;
    if (fx != 0.f) idx[e + 0] = (int)fx - 1;
    if (fy != 0.f) idx[e + 1] = (int)fy - 1;
    if (fz != 0.f) idx[e + 2] = (int)fz - 1;
    if (fw != 0.f) idx[e + 3] = (int)fw - 1;

#if __CUDA_ARCH__ >= 900
    cudaTriggerProgrammaticLaunchCompletion();
#endif
}

// ---------------------------------------------------------------------------
// Kernel 2: fused gather + 2-layer MLP per edge.
// B[e] = [X[idx_o[e]], X[idx_i[e]]] (22) -> tanh(.@W1+b1) (8) -> sigmoid(.@W2+b2)
// Launched with PDL: weight preload overlaps the scan tail; grid-dependency
// sync before reading the scan's index output.
// ---------------------------------------------------------------------------
__global__ void __launch_bounds__(256)
edge_mlp_kernel(const float* __restrict__ X,
                const float* __restrict__ W1, const float* __restrict__ b1,
                const float* __restrict__ W2, const float* __restrict__ b2,
                float* __restrict__ out)
{
    __shared__ float sW1[2 * FEAT * HID];  // [22][8] = 176 floats
    __shared__ float sb1[HID];
    __shared__ float sW2[HID];
    __shared__ float sb2;

    const int t = threadIdx.x;
    // Scan-independent preamble: runs while the scan drains (PDL overlap)
    for (int i = t; i < 2 * FEAT * HID; i += blockDim.x) sW1[i] = W1[i];
    if (t < HID)  { sb1[t] = b1[t]; sW2[t] = W2[t]; }
    if (t == 0)   sb2 = b2[0];
    __syncthreads();

#if __CUDA_ARCH__ >= 900
    cudaGridDependencySynchronize();   // scan grid fully complete past this point
#endif

    const int e = blockIdx.x * blockDim.x + t;
    if (e >= N_EDGES) return;

    const float* __restrict__ xo = X + (size_t)g_idx_o[e] * FEAT;
    const float* __restrict__ xi = X + (size_t)g_idx_i[e] * FEAT;

    float h[HID];
#pragma unroll
    for (int j = 0; j < HID; ++j) h[j] = sb1[j];

#pragma unroll
    for (int f = 0; f < FEAT; ++f) {
        const float v = __ldg(xo + f);
#pragma unroll
        for (int j = 0; j < HID; ++j) h[j] = fmaf(v, sW1[f * HID + j], h[j]);
    }
#pragma unroll
    for (int f = 0; f < FEAT; ++f) {
        const float v = __ldg(xi + f);
#pragma unroll
        for (int j = 0; j < HID; ++j) h[j] = fmaf(v, sW1[(FEAT + f) * HID + j], h[j]);
    }

    float s = sb2;
#pragma unroll
    for (int j = 0; j < HID; ++j) s = fmaf(tanhf(h[j]), sW2[j], s);

    out[e] = 1.0f / (1.0f + expf(-s));
}

// ---------------------------------------------------------------------------
// Inputs (metadata order): X, Ri, Ro, W1, b1, W2, b2. Output: float [N_EDGES].
// ---------------------------------------------------------------------------
extern "C" void kernel_launch(void* const* d_in, const int* in_sizes, int n_in,
                              void* d_out, int out_size)
{
    const float* X  = (const float*)d_in[0];
    const float* Ri = (const float*)d_in[1];
    const float* Ro = (const float*)d_in[2];
    const float* W1 = (const float*)d_in[3];
    const float* b1 = (const float*)d_in[4];
    const float* W2 = (const float*)d_in[5];
    const float* b2 = (const float*)d_in[6];
    float* out = (float*)d_out;

    // Scan: 32 edge-blocks x 128 n-slabs x 2 matrices = 8192 CTAs
    dim3 sgrid(EG / 256, NSLABS, 2);
    scan_onehot_kernel<<<sgrid, 256>>>(Ri, Ro);

    // MLP: 128 CTAs x 256 threads, programmatic dependent launch (overlaps
    // its launch latency + weight preload with the scan's drain).
    cudaLaunchConfig_t cfg = {};
    cfg.gridDim  = dim3(N_EDGES / 256);
    cfg.blockDim = dim3(256);
    cfg.dynamicSmemBytes = 0;
    cfg.stream = 0;
    cudaLaunchAttribute attrs[1];
    attrs[0].id = cudaLaunchAttributeProgrammaticStreamSerialization;
    attrs[0].val.programmaticStreamSerializationAllowed = 1;
    cfg.attrs = attrs;
    cfg.numAttrs = 1;
    cudaLaunchKernelEx(&cfg, edge_mlp_kernel, X, W1, b1, W2, b2, out);
}